// round 6
// baseline (speedup 1.0000x reference)
#include <cuda_runtime.h>
#include <math.h>
#include <stdint.h>

// Problem constants
#define NN   30000
#define NE   60000
#define FEAT 256
#define HID  1024
#define OUTD 256
#define RANK 64

// ---------------- scratch (device globals) ----------------
__device__ float g_embR    [NN * FEAT];   // tf32-rounded embedding
__device__ float g_emb_new [NN * RANK];
__device__ float g_hidden  [NN * HID];    // stored tf32-rounded
__device__ float g_emb_new2[NN * OUTD];
__device__ float g_residual[NN * OUTD];
__device__ float g_tee     [NE * 4 * RANK];
__device__ float g_esum2   [NE * OUTD];
__device__ float g_nodeacc [NN * OUTD];
__device__ float g_accR    [NN * RANK];   // stored tf32-rounded
__device__ int   g_offs    [NN + 1];
__device__ int   g_cursor  [NN];
__device__ int   g_csr     [NE * 4];
// transposed (K-major) weights, tf32-rounded: Wt[n][k]
__device__ float g_Wt1 [HID  * FEAT];
__device__ float g_Wt2 [OUTD * HID];
__device__ float g_WtA [OUTD * FEAT];
__device__ float g_WtP [RANK * FEAT];
__device__ float g_WtQ [OUTD * RANK];

// ---------------- helpers ----------------
__device__ __forceinline__ uint32_t smem_u32(const void* p) {
    uint32_t a;
    asm("{ .reg .u64 t; cvta.to.shared.u64 t, %1; cvt.u32.u64 %0, t; }" : "=r"(a) : "l"(p));
    return a;
}
__device__ __forceinline__ float tf32r(float x) {
    uint32_t u;
    asm("cvt.rna.tf32.f32 %0, %1;" : "=r"(u) : "f"(x));
    return __uint_as_float(u);
}
__device__ __forceinline__ void cp16(uint32_t dst, const void* src, int szbytes) {
    asm volatile("cp.async.ca.shared.global [%0], [%1], 16, %2;"
                 :: "r"(dst), "l"(src), "r"(szbytes) : "memory");
}
#define CP_COMMIT() asm volatile("cp.async.commit_group;" ::: "memory")
#define CP_WAIT(n)  asm volatile("cp.async.wait_group %0;" :: "n"(n) : "memory")

__device__ __forceinline__ void mma16n8k8(float* d, const uint32_t* a, const uint32_t* b) {
    asm volatile(
        "mma.sync.aligned.m16n8k8.row.col.f32.tf32.tf32.f32 "
        "{%0,%1,%2,%3}, {%4,%5,%6,%7}, {%8,%9}, {%0,%1,%2,%3};"
        : "+f"(d[0]), "+f"(d[1]), "+f"(d[2]), "+f"(d[3])
        : "r"(a[0]), "r"(a[1]), "r"(a[2]), "r"(a[3]), "r"(b[0]), "r"(b[1]));
}

// ---------------- embedding tf32 pre-round ----------------
__global__ void round_emb(const float4* __restrict__ src, float4* __restrict__ dst, int n4)
{
    int i = blockIdx.x * blockDim.x + threadIdx.x;
    if (i < n4) {
        float4 v = src[i];
        v.x = tf32r(v.x); v.y = tf32r(v.y); v.z = tf32r(v.z); v.w = tf32r(v.w);
        dst[i] = v;
    }
}

// ---------------- batched weight transpose (+ tf32 round) ----------------
struct TJob { const float* W; float* Wt; int K; int N; int tstart; };
__global__ void transpose5(TJob j0, TJob j1, TJob j2, TJob j3, TJob j4)
{
    __shared__ float t[32][33];
    int bx = blockIdx.x;
    TJob p;
    if      (bx >= j4.tstart) p = j4;
    else if (bx >= j3.tstart) p = j3;
    else if (bx >= j2.tstart) p = j2;
    else if (bx >= j1.tstart) p = j1;
    else                      p = j0;
    int tt = bx - p.tstart;
    int tiles_n = p.N >> 5;
    int n0 = (tt % tiles_n) * 32, k0 = (tt / tiles_n) * 32;
    for (int i = threadIdx.y; i < 32; i += 8)
        t[i][threadIdx.x] = p.W[(size_t)(k0 + i) * p.N + n0 + threadIdx.x];
    __syncthreads();
    for (int i = threadIdx.y; i < 32; i += 8)
        p.Wt[(size_t)(n0 + i) * p.K + k0 + threadIdx.x] = tf32r(t[threadIdx.x][i]);
}

// ---------------- CSR offsets: single-block coarsened exclusive scan ----------------
__global__ __launch_bounds__(1024)
void scan_offsets(const int* __restrict__ deg, int* __restrict__ offs,
                  int* __restrict__ cursor, int N)
{
    const int tid = threadIdx.x;
    const int CE = (N + 1023) / 1024;
    int start = tid * CE;
    int vals[32];
    int local = 0;
    for (int j = 0; j < CE; j++) {
        int i = start + j;
        int v = (i < N) ? deg[i] : 0;
        vals[j] = local;
        local += v;
    }
    __shared__ int warpsum[32];
    int lane = tid & 31, w = tid >> 5;
    int x = local;
    #pragma unroll
    for (int o = 1; o < 32; o <<= 1) { int y = __shfl_up_sync(~0u, x, o); if (lane >= o) x += y; }
    if (lane == 31) warpsum[w] = x;
    __syncthreads();
    if (w == 0) {
        int s = warpsum[lane];
        #pragma unroll
        for (int o = 1; o < 32; o <<= 1) { int y = __shfl_up_sync(~0u, s, o); if (lane >= o) s += y; }
        warpsum[lane] = s;
    }
    __syncthreads();
    int base = x - local + (w > 0 ? warpsum[w - 1] : 0);
    for (int j = 0; j < CE; j++) {
        int i = start + j;
        if (i < N) { offs[i] = base + vals[j]; cursor[i] = 0; }
    }
    if (tid == 1023) offs[N] = base + local;
}

__global__ void csr_fill(const int* __restrict__ inc_node, const int* __restrict__ inc_edge,
                         const int* __restrict__ inc_slot, int NINC)
{
    int i = blockIdx.x * blockDim.x + threadIdx.x;
    if (i < NINC) {
        int n = inc_node[i];
        int p = atomicAdd(&g_cursor[n], 1);
        g_csr[g_offs[n] + p] = (inc_edge[i] << 2) | inc_slot[i];
    }
}

// ---------------- tensor-core tf32 GEMM (mma.sync) ----------------
// CTA tile 256 x NT; 8 warps as 4(M) x 2(N); per-warp 64 x NT/2 (mt=4, nt=NT/16).
// mode bits: 0/1 -> (+bias(+biasRow)) / relu(...); 2 -> relu((acc+addSrc)/deg+bias)+resid;
// bit 4: tf32-round stored values.
template<int NT>
__global__ __launch_bounds__(256, 1)
void mma_gemm(const float* __restrict__ A, const float* __restrict__ Bt,
              const float* __restrict__ bias, const float* __restrict__ biasRow,
              float* __restrict__ C, int M, int N, int K, int mode,
              const float* __restrict__ addSrc, const float* __restrict__ resid,
              const int* __restrict__ degv)
{
    constexpr int ST = 36;
    constexpr int MT = 4;                  // 4 m-tiles of 16 per warp
    constexpr int NTILES = NT / 16;        // n-tiles of 8 per warp
    extern __shared__ float dyn[];
    float* Asm = dyn;                      // 2 bufs x 256 x ST
    float* Bsm = dyn + 2 * 256 * ST;       // 2 bufs x NT x ST

    const int tid  = threadIdx.x;
    const int wid  = tid >> 5;
    const int lane = tid & 31;
    const int grp  = lane >> 2;
    const int tig  = lane & 3;
    const int warpM = (wid & 3) * 64;
    const int warpN = (wid >> 2) * (NT / 2);
    const int rowBase = blockIdx.y * 256;
    const int colBase = blockIdx.x * NT;
    const int baseMode = mode & 3;
    const bool roundOut = (mode & 4) != 0;

    float acc[MT][NTILES][4];
    #pragma unroll
    for (int mt = 0; mt < MT; mt++)
        #pragma unroll
        for (int nt = 0; nt < NTILES; nt++)
            #pragma unroll
            for (int i = 0; i < 4; i++) acc[mt][nt][i] = 0.f;

    const uint32_t asm_base = smem_u32(Asm);
    const uint32_t bsm_base = smem_u32(Bsm);

    auto loadChunk = [&](int c, int buf) {
        // A: 256 rows x 32 floats = 2048 float4; 8 per thread
        #pragma unroll
        for (int i = 0; i < 8; i++) {
            int idx = tid + (i << 8);
            int r = idx >> 3, f4 = idx & 7;
            int gr = rowBase + r;
            const float* src = A + (size_t)gr * K + (c << 5) + (f4 << 2);
            uint32_t dst = asm_base + (buf * 256 * ST + r * ST + (f4 << 2)) * 4;
            cp16(dst, src, gr < M ? 16 : 0);
        }
        // B: NT rows x 32 floats
        #pragma unroll
        for (int i = 0; i < NT / 32; i++) {
            int idx = tid + (i << 8);
            int r = idx >> 3, f4 = idx & 7;
            const float* src = Bt + (size_t)(colBase + r) * K + (c << 5) + (f4 << 2);
            uint32_t dst = bsm_base + (buf * NT * ST + r * ST + (f4 << 2)) * 4;
            cp16(dst, src, 16);
        }
        CP_COMMIT();
    };

    const int nch = K >> 5;
    loadChunk(0, 0);

    for (int c = 0; c < nch; ++c) {
        const int buf = c & 1;
        if (c + 1 < nch) { loadChunk(c + 1, buf ^ 1); CP_WAIT(1); }
        else             { CP_WAIT(0); }
        __syncthreads();

        const float* ab = Asm + buf * 256 * ST;
        const float* bb = Bsm + buf * NT * ST;
        #pragma unroll
        for (int ks = 0; ks < 4; ++ks) {
            const int kb = ks << 3;
            uint32_t afr[MT][4];
            #pragma unroll
            for (int mt = 0; mt < MT; mt++) {
                int base = (warpM + mt * 16 + grp) * ST + kb + tig;
                afr[mt][0] = __float_as_uint(ab[base]);
                afr[mt][1] = __float_as_uint(ab[base + 8 * ST]);
                afr[mt][2] = __float_as_uint(ab[base + 4]);
                afr[mt][3] = __float_as_uint(ab[base + 8 * ST + 4]);
            }
            uint32_t bfr[NTILES][2];
            #pragma unroll
            for (int nt = 0; nt < NTILES; nt++) {
                int base = (warpN + nt * 8 + grp) * ST + kb + tig;
                bfr[nt][0] = __float_as_uint(bb[base]);
                bfr[nt][1] = __float_as_uint(bb[base + 4]);
            }
            #pragma unroll
            for (int mt = 0; mt < MT; mt++)
                #pragma unroll
                for (int nt = 0; nt < NTILES; nt++)
                    mma16n8k8(acc[mt][nt], afr[mt], bfr[nt]);
        }
        __syncthreads();
    }

    #pragma unroll
    for (int mt = 0; mt < MT; mt++) {
        #pragma unroll
        for (int nt = 0; nt < NTILES; nt++) {
            int col = colBase + warpN + nt * 8 + (tig << 1);
            float b0 = bias[col], b1 = bias[col + 1];
            if (baseMode != 2 && biasRow) { b0 += biasRow[col]; b1 += biasRow[col + 1]; }
            #pragma unroll
            for (int h = 0; h < 2; h++) {
                int row = rowBase + warpM + mt * 16 + grp + h * 8;
                if (row >= M) continue;
                float v0 = acc[mt][nt][2 * h];
                float v1 = acc[mt][nt][2 * h + 1];
                if (baseMode == 2) {
                    float rd = 1.0f / (float)degv[row];
                    size_t base = (size_t)row * N + col;
                    v0 = fmaxf((v0 + addSrc[base])     * rd + b0, 0.f) + resid[base];
                    v1 = fmaxf((v1 + addSrc[base + 1]) * rd + b1, 0.f) + resid[base + 1];
                } else {
                    v0 += b0; v1 += b1;
                    if (baseMode == 1) { v0 = fmaxf(v0, 0.f); v1 = fmaxf(v1, 0.f); }
                }
                if (roundOut) { v0 = tf32r(v0); v1 = tf32r(v1); }
                *(float2*)(C + (size_t)row * N + col) = make_float2(v0, v1);
            }
        }
    }
}

// ---------------- edge kernel: 2 edges per 256-thread block ----------------
__global__ __launch_bounds__(256)
void edge_kernel(const float* __restrict__ global_emb,
                 const int* __restrict__ edge_nodes,
                 const int* __restrict__ edge_size,
                 const int* __restrict__ node_degree,
                 int E)
{
    __shared__ int   s_nodes[2][4];
    __shared__ float s_scale[2][4];
    __shared__ int   s_size[2];

    const int half = threadIdx.x >> 7;
    const int lt   = threadIdx.x & 127;
    const int e    = blockIdx.x * 2 + half;
    const bool active = (e < E);

    if (active && lt < 4) {
        int sz = edge_size[e];
        if (lt == 0) s_size[half] = sz;
        int n = edge_nodes[e * 4 + lt];
        s_nodes[half][lt] = n;
        float a = (sz == 1) ? 1.0f : (sz <= 3 ? (1.0f / 3.0f) : 0.25f);
        s_scale[half][lt] = powf((float)node_degree[n], a);
    }
    __syncthreads();
    if (!active) return;

    const int sz = s_size[half];
    const int k = 4 - sz;
    const float invf = (sz == 3) ? 0.5f : (sz == 4 ? (1.0f / 6.0f) : 1.0f);

    if (lt < RANK) {
        const int r = lt;
        float g = global_emb[r];
        float gf = (k == 0) ? 1.0f : (k == 1 ? g : g * g);
        float t[4];
        #pragma unroll
        for (int s = 0; s < 4; s++)
            t[s] = (s < sz) ? s_scale[half][s] * g_emb_new[(size_t)s_nodes[half][s] * RANK + r] : 1.0f;
        float loo[4];
        loo[0] = t[1] * t[2] * t[3];
        loo[1] = t[0] * t[2] * t[3];
        loo[2] = t[0] * t[1] * t[3];
        loo[3] = t[0] * t[1] * t[2];
        float f = gf * invf;
        for (int s = 0; s < sz; s++)
            g_tee[((size_t)e * 4 + s) * RANK + r] = tanhf(loo[s] * f);
    }

    {
        float sum0 = 0.f, sum1 = 0.f;
        for (int s = 0; s < sz; s++) {
            const float* row = g_emb_new2 + (size_t)s_nodes[half][s] * OUTD;
            sum0 += row[lt];
            sum1 += row[lt + 128];
        }
        g_esum2[(size_t)e * OUTD + lt]       = fmaxf(sum0, 0.f);
        g_esum2[(size_t)e * OUTD + lt + 128] = fmaxf(sum1, 0.f);
    }
}

// ---------------- node-major gather (unrolled x2 for MLP) ----------------
__global__ __launch_bounds__(256)
void node_gather()
{
    int n = blockIdx.x;
    int tid = threadIdx.x;
    int s0 = g_offs[n], s1 = g_offs[n + 1];
    float acc0 = 0.f, acc1 = 0.f;
    float accr0 = 0.f, accr1 = 0.f;
    int j = s0;
    for (; j + 1 < s1; j += 2) {
        int codeA = g_csr[j], codeB = g_csr[j + 1];
        int eA = codeA >> 2, sA = codeA & 3;
        int eB = codeB >> 2, sB = codeB & 3;
        acc0 += g_esum2[(size_t)eA * OUTD + tid];
        acc1 += g_esum2[(size_t)eB * OUTD + tid];
        if (tid < RANK) {
            accr0 += g_tee[((size_t)eA * 4 + sA) * RANK + tid];
            accr1 += g_tee[((size_t)eB * 4 + sB) * RANK + tid];
        }
    }
    if (j < s1) {
        int code = g_csr[j];
        int e = code >> 2, s = code & 3;
        acc0 += g_esum2[(size_t)e * OUTD + tid];
        if (tid < RANK) accr0 += g_tee[((size_t)e * 4 + s) * RANK + tid];
    }
    g_nodeacc[(size_t)n * OUTD + tid] = acc0 + acc1;
    if (tid < RANK) g_accR[(size_t)n * RANK + tid] = tf32r(accr0 + accr1);
}

// ---------------- launch ----------------
extern "C" void kernel_launch(void* const* d_in, const int* in_sizes, int n_in,
                              void* d_out, int out_size)
{
    const float* embedding  = (const float*)d_in[0];
    const float* global_emb = (const float*)d_in[1];
    const float* pW         = (const float*)d_in[2];
    const float* pb         = (const float*)d_in[3];
    const float* qW         = (const float*)d_in[4];
    const float* qb         = (const float*)d_in[5];
    const float* p2W1       = (const float*)d_in[6];
    const float* p2b1       = (const float*)d_in[7];
    const float* p2W2       = (const float*)d_in[8];
    const float* p2b2       = (const float*)d_in[9];
    const float* aW         = (const float*)d_in[10];
    const float* ab         = (const float*)d_in[11];
    const int*   edge_nodes = (const int*)d_in[12];
    const int*   edge_size  = (const int*)d_in[14];
    const int*   node_deg   = (const int*)d_in[15];
    const int*   inc_node   = (const int*)d_in[16];
    const int*   inc_edge   = (const int*)d_in[17];
    const int*   inc_slot   = (const int*)d_in[18];

    const int N    = in_sizes[0] / FEAT;
    const int E    = in_sizes[14];
    const int NINC = in_sizes[16];

    float *p_embR, *p_emb_new, *p_hidden, *p_emb_new2, *p_residual, *p_nodeacc, *p_accR;
    float *p_Wt1, *p_Wt2, *p_WtA, *p_WtP, *p_WtQ;
    int *p_offs, *p_cursor;
    cudaGetSymbolAddress((void**)&p_embR,     g_embR);
    cudaGetSymbolAddress((void**)&p_emb_new,  g_emb_new);
    cudaGetSymbolAddress((void**)&p_hidden,   g_hidden);
    cudaGetSymbolAddress((void**)&p_emb_new2, g_emb_new2);
    cudaGetSymbolAddress((void**)&p_residual, g_residual);
    cudaGetSymbolAddress((void**)&p_nodeacc,  g_nodeacc);
    cudaGetSymbolAddress((void**)&p_accR,     g_accR);
    cudaGetSymbolAddress((void**)&p_offs,     g_offs);
    cudaGetSymbolAddress((void**)&p_cursor,   g_cursor);
    cudaGetSymbolAddress((void**)&p_Wt1, g_Wt1);
    cudaGetSymbolAddress((void**)&p_Wt2, g_Wt2);
    cudaGetSymbolAddress((void**)&p_WtA, g_WtA);
    cudaGetSymbolAddress((void**)&p_WtP, g_WtP);
    cudaGetSymbolAddress((void**)&p_WtQ, g_WtQ);

    const int SMEM128 = (2 * 256 * 36 + 2 * 128 * 36) * 4;  // 110592
    const int SMEM64  = (2 * 256 * 36 + 2 * 64  * 36) * 4;  // 92160
    cudaFuncSetAttribute(mma_gemm<128>, cudaFuncAttributeMaxDynamicSharedMemorySize, SMEM128);
    cudaFuncSetAttribute(mma_gemm<64>,  cudaFuncAttributeMaxDynamicSharedMemorySize, SMEM64);

    const int Mtiles = (N + 255) / 256;   // 118

    // 0: pre-round embedding to tf32
    {
        int n4 = N * FEAT / 4;
        round_emb<<<(n4 + 255) / 256, 256>>>((const float4*)embedding, (float4*)p_embR, n4);
    }
    // 1: all 5 weight transposes
    {
        TJob j0 = { p2W1, p_Wt1, FEAT, HID,  0   };
        TJob j1 = { p2W2, p_Wt2, HID,  OUTD, 256 };
        TJob j2 = { aW,   p_WtA, FEAT, OUTD, 512 };
        TJob j3 = { pW,   p_WtP, FEAT, RANK, 576 };
        TJob j4 = { qW,   p_WtQ, RANK, OUTD, 592 };
        transpose5<<<608, dim3(32, 8)>>>(j0, j1, j2, j3, j4);
    }
    // 2: CSR offsets
    scan_offsets<<<1, 1024>>>(node_deg, p_offs, p_cursor, N);
    // 3: G2 (ncu target) hidden = relu(embR @ p2W1 + ...), stored tf32   [N x 1024]
    mma_gemm<128><<<dim3(HID / 128, Mtiles), 256, SMEM128>>>(
        p_embR, p_Wt1, p2b1, p2W1 + FEAT * HID, p_hidden, N, HID, FEAT, 1 | 4,
        nullptr, nullptr, nullptr);
    // 4: CSR fill
    csr_fill<<<(NINC + 255) / 256, 256>>>(inc_node, inc_edge, inc_slot, NINC);
    // 5: G1 emb_new = embR @ pW^T + (pb + pW[256,:])                      [N x 64]
    mma_gemm<64><<<dim3(1, Mtiles), 256, SMEM64>>>(
        p_embR, p_WtP, pb, pW + FEAT * RANK, p_emb_new, N, RANK, FEAT, 0,
        nullptr, nullptr, nullptr);
    // 6: G3 emb_new2 = hidden @ p2W2 + p2b2                               [N x 256]
    mma_gemm<128><<<dim3(OUTD / 128, Mtiles), 256, SMEM128>>>(
        p_hidden, p_Wt2, p2b2, nullptr, p_emb_new2, N, OUTD, HID, 0,
        nullptr, nullptr, nullptr);
    // 7: G4 residual = relu(embR @ aW + ...)                              [N x 256]
    mma_gemm<128><<<dim3(OUTD / 128, Mtiles), 256, SMEM128>>>(
        p_embR, p_WtA, ab, aW + FEAT * OUTD, p_residual, N, OUTD, FEAT, 1,
        nullptr, nullptr, nullptr);
    // 8: edge-level tanh(ee) + relu(esum2)
    edge_kernel<<<(E + 1) / 2, 256>>>(global_emb, edge_nodes, edge_size, node_deg, E);
    // 9: node-major gather
    node_gather<<<N, 256>>>();
    // 10: final fused GEMM: out = relu((accR@qW^T + acc256)/deg + qb) + residual
    mma_gemm<128><<<dim3(OUTD / 128, Mtiles), 256, SMEM128>>>(
        p_accR, p_WtQ, qb, nullptr, (float*)d_out, N, OUTD, RANK, 2,
        p_nodeacc, p_residual, node_deg);
}

// round 7
// speedup vs baseline: 1.0637x; 1.0637x over previous
#include <cuda_runtime.h>
#include <math.h>
#include <stdint.h>

// Problem constants
#define NN   30000
#define NE   60000
#define FEAT 256
#define HID  1024
#define OUTD 256
#define RANK 64

// ---------------- scratch (device globals) ----------------
__device__ float g_embR    [NN * FEAT];
__device__ float g_emb_new [NN * RANK];
__device__ float g_hidden  [NN * HID];    // stored tf32-rounded
__device__ float g_emb_new2[NN * OUTD];
__device__ float g_residual[NN * OUTD];
__device__ float g_tee     [NE * 4 * RANK];
__device__ float g_esum2   [NE * OUTD];
__device__ float g_nodeacc [NN * OUTD];
__device__ float g_accR    [NN * RANK];   // stored tf32-rounded
__device__ int   g_offs    [NN + 1];
__device__ int   g_cursor  [NN];
__device__ int   g_csr     [NE * 4];
// K-major tf32-rounded weights
__device__ float g_WtC [(HID + OUTD) * FEAT];  // [Wt1 ; WtA]  1280 x 256
__device__ float g_Wt2 [OUTD * HID];
__device__ float g_WtP [RANK * FEAT];
__device__ float g_WtQ [OUTD * RANK];
// folded biases
__device__ float g_biasC [HID + OUTD];
__device__ float g_biasP [RANK];

// ---------------- helpers ----------------
__device__ __forceinline__ uint32_t smem_u32(const void* p) {
    uint32_t a;
    asm("{ .reg .u64 t; cvta.to.shared.u64 t, %1; cvt.u32.u64 %0, t; }" : "=r"(a) : "l"(p));
    return a;
}
__device__ __forceinline__ float tf32r(float x) {
    uint32_t u;
    asm("cvt.rna.tf32.f32 %0, %1;" : "=r"(u) : "f"(x));
    return __uint_as_float(u);
}
__device__ __forceinline__ void cp16(uint32_t dst, const void* src, int szbytes) {
    asm volatile("cp.async.ca.shared.global [%0], [%1], 16, %2;"
                 :: "r"(dst), "l"(src), "r"(szbytes) : "memory");
}
#define CP_COMMIT() asm volatile("cp.async.commit_group;" ::: "memory")
#define CP_WAIT(n)  asm volatile("cp.async.wait_group %0;" :: "n"(n) : "memory")

__device__ __forceinline__ void mma16n8k8(float* d, const uint32_t* a, const uint32_t* b) {
    asm volatile(
        "mma.sync.aligned.m16n8k8.row.col.f32.tf32.tf32.f32 "
        "{%0,%1,%2,%3}, {%4,%5,%6,%7}, {%8,%9}, {%0,%1,%2,%3};"
        : "+f"(d[0]), "+f"(d[1]), "+f"(d[2]), "+f"(d[3])
        : "r"(a[0]), "r"(a[1]), "r"(a[2]), "r"(a[3]), "r"(b[0]), "r"(b[1]));
}

// ---------------- embedding tf32 pre-round ----------------
__global__ void round_emb(const float4* __restrict__ src, float4* __restrict__ dst, int n4)
{
    int i = blockIdx.x * blockDim.x + threadIdx.x;
    if (i < n4) {
        float4 v = src[i];
        v.x = tf32r(v.x); v.y = tf32r(v.y); v.z = tf32r(v.z); v.w = tf32r(v.w);
        dst[i] = v;
    }
}

// ---------------- batched weight transpose (+ tf32 round) ----------------
struct TJob { const float* W; float* Wt; int K; int N; int tstart; };
__global__ void transpose5(TJob j0, TJob j1, TJob j2, TJob j3, TJob j4)
{
    __shared__ float t[32][33];
    int bx = blockIdx.x;
    TJob p;
    if      (bx >= j4.tstart) p = j4;
    else if (bx >= j3.tstart) p = j3;
    else if (bx >= j2.tstart) p = j2;
    else if (bx >= j1.tstart) p = j1;
    else                      p = j0;
    int tt = bx - p.tstart;
    int tiles_n = p.N >> 5;
    int n0 = (tt % tiles_n) * 32, k0 = (tt / tiles_n) * 32;
    for (int i = threadIdx.y; i < 32; i += 8)
        t[i][threadIdx.x] = p.W[(size_t)(k0 + i) * p.N + n0 + threadIdx.x];
    __syncthreads();
    for (int i = threadIdx.y; i < 32; i += 8)
        p.Wt[(size_t)(n0 + i) * p.K + k0 + threadIdx.x] = tf32r(t[threadIdx.x][i]);
}

// ---------------- folded-bias prep ----------------
__global__ void prep_bias(const float* __restrict__ p2b1, const float* __restrict__ p2W1,
                          const float* __restrict__ ab_,  const float* __restrict__ aW_,
                          const float* __restrict__ pb_,  const float* __restrict__ pW_)
{
    int i = blockIdx.x * blockDim.x + threadIdx.x;
    if (i < HID) g_biasC[i] = p2b1[i] + p2W1[FEAT * HID + i];
    else if (i < HID + OUTD) { int c = i - HID; g_biasC[i] = ab_[c] + aW_[FEAT * OUTD + c]; }
    if (i < RANK) g_biasP[i] = pb_[i] + pW_[FEAT * RANK + i];
}

// ---------------- CSR offsets: single-block coarsened exclusive scan ----------------
__global__ __launch_bounds__(1024)
void scan_offsets(const int* __restrict__ deg, int* __restrict__ offs,
                  int* __restrict__ cursor, int N)
{
    const int tid = threadIdx.x;
    const int CE = (N + 1023) / 1024;
    int start = tid * CE;
    int vals[32];
    int local = 0;
    for (int j = 0; j < CE; j++) {
        int i = start + j;
        int v = (i < N) ? deg[i] : 0;
        vals[j] = local;
        local += v;
    }
    __shared__ int warpsum[32];
    int lane = tid & 31, w = tid >> 5;
    int x = local;
    #pragma unroll
    for (int o = 1; o < 32; o <<= 1) { int y = __shfl_up_sync(~0u, x, o); if (lane >= o) x += y; }
    if (lane == 31) warpsum[w] = x;
    __syncthreads();
    if (w == 0) {
        int s = warpsum[lane];
        #pragma unroll
        for (int o = 1; o < 32; o <<= 1) { int y = __shfl_up_sync(~0u, s, o); if (lane >= o) s += y; }
        warpsum[lane] = s;
    }
    __syncthreads();
    int base = x - local + (w > 0 ? warpsum[w - 1] : 0);
    for (int j = 0; j < CE; j++) {
        int i = start + j;
        if (i < N) { offs[i] = base + vals[j]; cursor[i] = 0; }
    }
    if (tid == 1023) offs[N] = base + local;
}

__global__ void csr_fill(const int* __restrict__ inc_node, const int* __restrict__ inc_edge,
                         const int* __restrict__ inc_slot, int NINC)
{
    int i = blockIdx.x * blockDim.x + threadIdx.x;
    if (i < NINC) {
        int n = inc_node[i];
        int p = atomicAdd(&g_cursor[n], 1);
        g_csr[g_offs[n] + p] = (inc_edge[i] << 2) | inc_slot[i];
    }
}

// ---------------- tensor-core tf32 GEMM (mma.sync; R5 geometry: 128 x NT, occ 2) ----------------
// mode 0: C[row*N+col] = acc + bias[col]
// mode 2: out = relu((acc + addSrc)/deg + bias) + resid      (final fusion)
// mode 3: split: col<1024 -> relu(acc+bias) tf32-rounded -> Chid (stride 1024)
//                col>=1024 -> relu(acc+bias) -> Cres (stride 256)
template<int NT>
__global__ __launch_bounds__(256, 2)
void mma_gemm(const float* __restrict__ A, const float* __restrict__ Bt,
              const float* __restrict__ bias,
              float* __restrict__ C, float* __restrict__ C2,
              int M, int N, int K, int mode,
              const float* __restrict__ addSrc, const float* __restrict__ resid,
              const int* __restrict__ degv)
{
    constexpr int ST = 36;
    constexpr int NTILES = NT / 16;
    extern __shared__ float dyn[];
    float* Asm = dyn;                      // 2 bufs x 128 x ST
    float* Bsm = dyn + 2 * 128 * ST;       // 2 bufs x NT x ST

    const int tid  = threadIdx.x;
    const int wid  = tid >> 5;
    const int lane = tid & 31;
    const int grp  = lane >> 2;
    const int tig  = lane & 3;
    const int warpM = (wid & 3) * 32;
    const int warpN = (wid >> 2) * (NT / 2);
    const int rowBase = blockIdx.y * 128;
    const int colBase = blockIdx.x * NT;

    float acc[2][NTILES][4];
    #pragma unroll
    for (int mt = 0; mt < 2; mt++)
        #pragma unroll
        for (int nt = 0; nt < NTILES; nt++)
            #pragma unroll
            for (int i = 0; i < 4; i++) acc[mt][nt][i] = 0.f;

    const uint32_t asm_base = smem_u32(Asm);
    const uint32_t bsm_base = smem_u32(Bsm);

    auto loadChunk = [&](int c, int buf) {
        #pragma unroll
        for (int i = 0; i < 4; i++) {
            int idx = tid + (i << 8);
            int r = idx >> 3, f4 = idx & 7;
            int gr = rowBase + r;
            const float* src = A + (size_t)gr * K + (c << 5) + (f4 << 2);
            uint32_t dst = asm_base + (buf * 128 * ST + r * ST + (f4 << 2)) * 4;
            cp16(dst, src, gr < M ? 16 : 0);
        }
        #pragma unroll
        for (int i = 0; i < NT / 32; i++) {
            int idx = tid + (i << 8);
            int r = idx >> 3, f4 = idx & 7;
            const float* src = Bt + (size_t)(colBase + r) * K + (c << 5) + (f4 << 2);
            uint32_t dst = bsm_base + (buf * NT * ST + r * ST + (f4 << 2)) * 4;
            cp16(dst, src, 16);
        }
        CP_COMMIT();
    };

    const int nch = K >> 5;
    loadChunk(0, 0);

    for (int c = 0; c < nch; ++c) {
        const int buf = c & 1;
        if (c + 1 < nch) { loadChunk(c + 1, buf ^ 1); CP_WAIT(1); }
        else             { CP_WAIT(0); }
        __syncthreads();

        const float* ab = Asm + buf * 128 * ST;
        const float* bb = Bsm + buf * NT * ST;
        #pragma unroll
        for (int ks = 0; ks < 4; ++ks) {
            const int kb = ks << 3;
            uint32_t afr[2][4];
            #pragma unroll
            for (int mt = 0; mt < 2; mt++) {
                int base = (warpM + mt * 16 + grp) * ST + kb + tig;
                afr[mt][0] = __float_as_uint(ab[base]);
                afr[mt][1] = __float_as_uint(ab[base + 8 * ST]);
                afr[mt][2] = __float_as_uint(ab[base + 4]);
                afr[mt][3] = __float_as_uint(ab[base + 8 * ST + 4]);
            }
            uint32_t bfr[NTILES][2];
            #pragma unroll
            for (int nt = 0; nt < NTILES; nt++) {
                int base = (warpN + nt * 8 + grp) * ST + kb + tig;
                bfr[nt][0] = __float_as_uint(bb[base]);
                bfr[nt][1] = __float_as_uint(bb[base + 4]);
            }
            #pragma unroll
            for (int mt = 0; mt < 2; mt++)
                #pragma unroll
                for (int nt = 0; nt < NTILES; nt++)
                    mma16n8k8(acc[mt][nt], afr[mt], bfr[nt]);
        }
        __syncthreads();
    }

    #pragma unroll
    for (int mt = 0; mt < 2; mt++) {
        #pragma unroll
        for (int nt = 0; nt < NTILES; nt++) {
            int col = colBase + warpN + nt * 8 + (tig << 1);
            float b0 = bias[col], b1 = bias[col + 1];
            #pragma unroll
            for (int h = 0; h < 2; h++) {
                int row = rowBase + warpM + mt * 16 + grp + h * 8;
                if (row >= M) continue;
                float v0 = acc[mt][nt][2 * h];
                float v1 = acc[mt][nt][2 * h + 1];
                if (mode == 3) {
                    v0 = fmaxf(v0 + b0, 0.f);
                    v1 = fmaxf(v1 + b1, 0.f);
                    if (col < HID) {
                        *(float2*)(C + (size_t)row * HID + col) =
                            make_float2(tf32r(v0), tf32r(v1));
                    } else {
                        *(float2*)(C2 + (size_t)row * OUTD + (col - HID)) =
                            make_float2(v0, v1);
                    }
                } else if (mode == 2) {
                    float rd = 1.0f / (float)degv[row];
                    size_t base = (size_t)row * N + col;
                    v0 = fmaxf((v0 + addSrc[base])     * rd + b0, 0.f) + resid[base];
                    v1 = fmaxf((v1 + addSrc[base + 1]) * rd + b1, 0.f) + resid[base + 1];
                    *(float2*)(C + base) = make_float2(v0, v1);
                } else {
                    *(float2*)(C + (size_t)row * N + col) = make_float2(v0 + b0, v1 + b1);
                }
            }
        }
    }
}

// ---------------- edge kernel: 2 edges per 256-thread block ----------------
__global__ __launch_bounds__(256)
void edge_kernel(const float* __restrict__ global_emb,
                 const int* __restrict__ edge_nodes,
                 const int* __restrict__ edge_size,
                 const int* __restrict__ node_degree,
                 int E)
{
    __shared__ int   s_nodes[2][4];
    __shared__ float s_scale[2][4];
    __shared__ int   s_size[2];

    const int half = threadIdx.x >> 7;
    const int lt   = threadIdx.x & 127;
    const int e    = blockIdx.x * 2 + half;
    const bool active = (e < E);

    if (active && lt < 4) {
        int sz = edge_size[e];
        if (lt == 0) s_size[half] = sz;
        int n = edge_nodes[e * 4 + lt];
        s_nodes[half][lt] = n;
        float a = (sz == 1) ? 1.0f : (sz <= 3 ? (1.0f / 3.0f) : 0.25f);
        s_scale[half][lt] = __powf((float)node_degree[n], a);
    }
    __syncthreads();
    if (!active) return;

    const int sz = s_size[half];
    const int k = 4 - sz;
    const float invf = (sz == 3) ? 0.5f : (sz == 4 ? (1.0f / 6.0f) : 1.0f);

    if (lt < RANK) {
        const int r = lt;
        float g = global_emb[r];
        float gf = (k == 0) ? 1.0f : (k == 1 ? g : g * g);
        float t[4];
        #pragma unroll
        for (int s = 0; s < 4; s++)
            t[s] = (s < sz) ? s_scale[half][s] * g_emb_new[(size_t)s_nodes[half][s] * RANK + r] : 1.0f;
        float loo[4];
        loo[0] = t[1] * t[2] * t[3];
        loo[1] = t[0] * t[2] * t[3];
        loo[2] = t[0] * t[1] * t[3];
        loo[3] = t[0] * t[1] * t[2];
        float f = gf * invf;
        for (int s = 0; s < sz; s++)
            g_tee[((size_t)e * 4 + s) * RANK + r] = tanhf(loo[s] * f);
    }

    {
        float sum0 = 0.f, sum1 = 0.f;
        for (int s = 0; s < sz; s++) {
            const float* row = g_emb_new2 + (size_t)s_nodes[half][s] * OUTD;
            sum0 += row[lt];
            sum1 += row[lt + 128];
        }
        g_esum2[(size_t)e * OUTD + lt]       = fmaxf(sum0, 0.f);
        g_esum2[(size_t)e * OUTD + lt + 128] = fmaxf(sum1, 0.f);
    }
}

// ---------------- node-major gather (unrolled x2 for MLP) ----------------
__global__ __launch_bounds__(256)
void node_gather()
{
    int n = blockIdx.x;
    int tid = threadIdx.x;
    int s0 = g_offs[n], s1 = g_offs[n + 1];
    float acc0 = 0.f, acc1 = 0.f;
    float accr0 = 0.f, accr1 = 0.f;
    int j = s0;
    for (; j + 1 < s1; j += 2) {
        int codeA = g_csr[j], codeB = g_csr[j + 1];
        int eA = codeA >> 2, sA = codeA & 3;
        int eB = codeB >> 2, sB = codeB & 3;
        acc0 += g_esum2[(size_t)eA * OUTD + tid];
        acc1 += g_esum2[(size_t)eB * OUTD + tid];
        if (tid < RANK) {
            accr0 += g_tee[((size_t)eA * 4 + sA) * RANK + tid];
            accr1 += g_tee[((size_t)eB * 4 + sB) * RANK + tid];
        }
    }
    if (j < s1) {
        int code = g_csr[j];
        int e = code >> 2, s = code & 3;
        acc0 += g_esum2[(size_t)e * OUTD + tid];
        if (tid < RANK) accr0 += g_tee[((size_t)e * 4 + s) * RANK + tid];
    }
    g_nodeacc[(size_t)n * OUTD + tid] = acc0 + acc1;
    if (tid < RANK) g_accR[(size_t)n * RANK + tid] = tf32r(accr0 + accr1);
}

// ---------------- launch ----------------
extern "C" void kernel_launch(void* const* d_in, const int* in_sizes, int n_in,
                              void* d_out, int out_size)
{
    const float* embedding  = (const float*)d_in[0];
    const float* global_emb = (const float*)d_in[1];
    const float* pW         = (const float*)d_in[2];
    const float* pb         = (const float*)d_in[3];
    const float* qW         = (const float*)d_in[4];
    const float* qb         = (const float*)d_in[5];
    const float* p2W1       = (const float*)d_in[6];
    const float* p2b1       = (const float*)d_in[7];
    const float* p2W2       = (const float*)d_in[8];
    const float* p2b2       = (const float*)d_in[9];
    const float* aW         = (const float*)d_in[10];
    const float* ab         = (const float*)d_in[11];
    const int*   edge_nodes = (const int*)d_in[12];
    const int*   edge_size  = (const int*)d_in[14];
    const int*   node_deg   = (const int*)d_in[15];
    const int*   inc_node   = (const int*)d_in[16];
    const int*   inc_edge   = (const int*)d_in[17];
    const int*   inc_slot   = (const int*)d_in[18];

    const int N    = in_sizes[0] / FEAT;
    const int E    = in_sizes[14];
    const int NINC = in_sizes[16];

    float *p_embR, *p_emb_new, *p_hidden, *p_emb_new2, *p_residual, *p_nodeacc, *p_accR;
    float *p_WtC, *p_Wt2, *p_WtP, *p_WtQ, *p_biasC, *p_biasP;
    int *p_offs, *p_cursor;
    cudaGetSymbolAddress((void**)&p_embR,     g_embR);
    cudaGetSymbolAddress((void**)&p_emb_new,  g_emb_new);
    cudaGetSymbolAddress((void**)&p_hidden,   g_hidden);
    cudaGetSymbolAddress((void**)&p_emb_new2, g_emb_new2);
    cudaGetSymbolAddress((void**)&p_residual, g_residual);
    cudaGetSymbolAddress((void**)&p_nodeacc,  g_nodeacc);
    cudaGetSymbolAddress((void**)&p_accR,     g_accR);
    cudaGetSymbolAddress((void**)&p_offs,     g_offs);
    cudaGetSymbolAddress((void**)&p_cursor,   g_cursor);
    cudaGetSymbolAddress((void**)&p_WtC,  g_WtC);
    cudaGetSymbolAddress((void**)&p_Wt2,  g_Wt2);
    cudaGetSymbolAddress((void**)&p_WtP,  g_WtP);
    cudaGetSymbolAddress((void**)&p_WtQ,  g_WtQ);
    cudaGetSymbolAddress((void**)&p_biasC, g_biasC);
    cudaGetSymbolAddress((void**)&p_biasP, g_biasP);

    const int SMEM128 = (2 * 128 * 36 + 2 * 128 * 36) * 4;  // 73728
    const int SMEM64  = (2 * 128 * 36 + 2 * 64  * 36) * 4;  // 55296
    cudaFuncSetAttribute(mma_gemm<128>, cudaFuncAttributeMaxDynamicSharedMemorySize, SMEM128);
    cudaFuncSetAttribute(mma_gemm<64>,  cudaFuncAttributeMaxDynamicSharedMemorySize, SMEM64);

    const int Mtiles = (N + 127) / 128;   // 235

    // 0: pre-round embedding to tf32
    {
        int n4 = N * FEAT / 4;
        round_emb<<<(n4 + 255) / 256, 256>>>((const float4*)embedding, (float4*)p_embR, n4);
    }
    // 1: weight transposes (Wt1 and WtA land in the combined buffer)
    {
        TJob j0 = { p2W1, p_WtC,               FEAT, HID,  0   };  // 256 tiles
        TJob j1 = { p2W2, p_Wt2,               HID,  OUTD, 256 };  // 256
        TJob j2 = { aW,   p_WtC + HID * FEAT,  FEAT, OUTD, 512 };  // 64
        TJob j3 = { pW,   p_WtP,               FEAT, RANK, 576 };  // 16
        TJob j4 = { qW,   p_WtQ,               RANK, OUTD, 592 };  // 16
        transpose5<<<608, dim3(32, 8)>>>(j0, j1, j2, j3, j4);
    }
    // 2: folded biases
    prep_bias<<<(HID + OUTD + 255) / 256, 256>>>(p2b1, p2W1, ab, aW, pb, pW);
    // 3: CSR offsets
    scan_offsets<<<1, 1024>>>(node_deg, p_offs, p_cursor, N);
    // 4: CSR fill
    csr_fill<<<(NINC + 255) / 256, 256>>>(inc_node, inc_edge, inc_slot, NINC);
    // 5 (ncu target): merged G2+G4: [hidden | residual] = relu(embR @ WtC^T + biasC)
    mma_gemm<128><<<dim3((HID + OUTD) / 128, Mtiles), 256, SMEM128>>>(
        p_embR, p_WtC, p_biasC, p_hidden, p_residual, N, HID + OUTD, FEAT, 3,
        nullptr, nullptr, nullptr);
    // 6: G1 emb_new = embR @ pW^T + biasP                              [N x 64]
    mma_gemm<64><<<dim3(1, Mtiles), 256, SMEM64>>>(
        p_embR, p_WtP, p_biasP, p_emb_new, nullptr, N, RANK, FEAT, 0,
        nullptr, nullptr, nullptr);
    // 7: G3 emb_new2 = hidden @ p2W2 + p2b2                            [N x 256]
    mma_gemm<128><<<dim3(OUTD / 128, Mtiles), 256, SMEM128>>>(
        p_hidden, p_Wt2, p2b2, p_emb_new2, nullptr, N, OUTD, HID, 0,
        nullptr, nullptr, nullptr);
    // 8: edge-level tanh(ee) + relu(esum2)
    edge_kernel<<<(E + 1) / 2, 256>>>(global_emb, edge_nodes, edge_size, node_deg, E);
    // 9: node-major gather
    node_gather<<<N, 256>>>();
    // 10: final fused GEMM: out = relu((accR@qW^T + acc256)/deg + qb) + residual
    mma_gemm<128><<<dim3(OUTD / 128, Mtiles), 256, SMEM128>>>(
        p_accR, p_WtQ, qb, (float*)d_out, nullptr, N, OUTD, RANK, 2,
        p_nodeacc, p_residual, node_deg);
}